// round 1
// baseline (speedup 1.0000x reference)
#include <cuda_runtime.h>
#include <cuda_bf16.h>

// ForgetMult: h_t = f_t*x_t + (1-f_t)*h_{t-1}, layout [T, B, H], all h_t written.
// One thread per (b,h) channel. T-loop unrolled by 16 with register double
// buffering so 32 LDGs are in flight per warp while the previous 16 steps
// compute -> hides the ~577cyc DRAM latency at only 7 warps/SM.

#define UNROLL 16

__global__ __launch_bounds__(224, 1)
void forgetmult_kernel(const float* __restrict__ f,
                       const float* __restrict__ x,
                       const float* __restrict__ h0,
                       float* __restrict__ out,
                       int n_channels, int T)
{
    int idx = blockIdx.x * blockDim.x + threadIdx.x;
    if (idx >= n_channels) return;

    float h = h0[idx];

    const float* fp = f + idx;
    const float* xp = x + idx;
    float*       op = out + idx;
    const long stride = (long)n_channels;           // elements between time steps
    const long ustep  = stride * UNROLL;

    int t = 0;
    int T_main = T - (T % UNROLL);

    if (T_main >= UNROLL) {
        float fa[UNROLL], xa[UNROLL];
        // prime buffer A with t = 0..UNROLL-1
        #pragma unroll
        for (int u = 0; u < UNROLL; u++) {
            fa[u] = fp[u * stride];
            xa[u] = xp[u * stride];
        }

        for (t = 0; t < T_main; t += UNROLL) {
            const bool more = (t + UNROLL) < T_main;
            float fb[UNROLL], xb[UNROLL];
            const float* fpn = fp + ustep;
            const float* xpn = xp + ustep;

            // issue next block's 32 loads first (front-batched MLP)
            #pragma unroll
            for (int u = 0; u < UNROLL; u++) {
                fb[u] = more ? fpn[u * stride] : 0.0f;
                xb[u] = more ? xpn[u * stride] : 0.0f;
            }

            // compute + store current block from registers
            #pragma unroll
            for (int u = 0; u < UNROLL; u++) {
                h = fmaf(1.0f - fa[u], h, fa[u] * xa[u]);
                op[u * stride] = h;
            }

            // rotate buffers (register renaming, no copies in SASS)
            #pragma unroll
            for (int u = 0; u < UNROLL; u++) {
                fa[u] = fb[u];
                xa[u] = xb[u];
            }

            fp += ustep; xp += ustep; op += ustep;
        }
    }

    // generic tail (T not multiple of UNROLL; unused for T=1024)
    for (; t < T; t++) {
        float fv = *fp, xv = *xp;
        h = fmaf(1.0f - fv, h, fv * xv);
        *op = h;
        fp += stride; xp += stride; op += stride;
    }
}

extern "C" void kernel_launch(void* const* d_in, const int* in_sizes, int n_in,
                              void* d_out, int out_size)
{
    const float* f  = (const float*)d_in[0];   // [T, B, H]
    const float* x  = (const float*)d_in[1];   // [T, B, H]
    const float* h0 = (const float*)d_in[2];   // [B, H]
    float* out = (float*)d_out;                // [T, B, H]

    const int n_channels = in_sizes[2];                 // B*H = 32768
    const int T = in_sizes[0] / n_channels;             // 1024

    const int threads = 224;                            // 7 warps -> 147 blocks == 1/SM
    const int blocks = (n_channels + threads - 1) / threads;

    forgetmult_kernel<<<blocks, threads>>>(f, x, h0, out, n_channels, T);
}